// round 11
// baseline (speedup 1.0000x reference)
#include <cuda_runtime.h>
#include <cuda_fp16.h>
#include <cstdint>

#define CIN   672
#define COUT  128
#define HW    49
#define NB    2
#define NREAL 98          // NB*HW
#define NPAD  112
#define KC    32
#define NKC   21
#define GRID  512
#define THREADS 512

#define LDA 20            // A row stride (half2 words): conflict-free frag reads
#define LDB 24            // B row stride (half2 words)
#define A_WORDS (COUT*LDA)   // 2560
#define B_WORDS (NPAD*LDB)   // 2688

#define OFF_SS 0                         // float2[672] = 1344 words
#define OFF_A0 1344
#define OFF_A1 (OFF_A0 + A_WORDS)
#define OFF_B0 (OFF_A1 + A_WORDS)
#define OFF_B1 (OFF_B0 + B_WORDS)
#define PIPE_WORDS (OFF_B1 + B_WORDS)    // 11840 words
#define PS 113
#define P_WORDS (COUT*PS)                // 14464 words
#define SMEM_WORDS (P_WORDS > PIPE_WORDS ? P_WORDS : PIPE_WORDS)
#define SMEM_BYTES (SMEM_WORDS*4)        // 57856 -> 2 CTAs/SM if regs <= 64

// ---- fp16 copy of W, produced once by K0 ----
__device__ __align__(16) __half W16_buf[COUT * CIN];

__global__ void w_cvt_kernel(const float* __restrict__ W) {
    int i = blockIdx.x * 256 + threadIdx.x;      // 84*256 = 21504 = 86016/4
    float4 v = *(const float4*)(W + i * 4);
    __half2 h0 = __floats2half2_rn(v.x, v.y);
    __half2 h1 = __floats2half2_rn(v.z, v.w);
    uint2 q;
    q.x = *(uint32_t*)&h0;
    q.y = *(uint32_t*)&h1;
    *(uint2*)(W16_buf + i * 4) = q;
}

__device__ __forceinline__ void hmma16816(float c[4],
    uint32_t a0, uint32_t a1, uint32_t a2, uint32_t a3, uint32_t b0, uint32_t b1)
{
    asm volatile(
        "mma.sync.aligned.m16n8k16.row.col.f32.f16.f16.f32 "
        "{%0,%1,%2,%3}, {%4,%5,%6,%7}, {%8,%9}, {%0,%1,%2,%3};"
        : "+f"(c[0]), "+f"(c[1]), "+f"(c[2]), "+f"(c[3])
        : "r"(a0), "r"(a1), "r"(a2), "r"(a3), "r"(b0), "r"(b1));
}
__device__ __forceinline__ uint32_t pack_h2(float lo, float hi) {
    __half2 h = __floats2half2_rn(lo, hi);
    return *reinterpret_cast<uint32_t*>(&h);
}
__device__ __forceinline__ uint32_t smem_u32(const void* p) {
    uint32_t a;
    asm("{ .reg .u64 t; cvta.to.shared.u64 t, %1; cvt.u32.u64 %0, t; }" : "=r"(a) : "l"(p));
    return a;
}
__device__ __forceinline__ void cp16(uint32_t dst, const void* src) {
    asm volatile("cp.async.cg.shared.global [%0], [%1], 16;" :: "r"(dst), "l"(src) : "memory");
}

extern __shared__ uint32_t sm[];

__global__ void __launch_bounds__(THREADS, 2)
bn_conv_w32(const float* __restrict__ x,
            const float* __restrict__ gamma,
            const float* __restrict__ beta,
            const float* __restrict__ rmean,
            const float* __restrict__ rvar,
            float* __restrict__ out)
{
    const int tid  = threadIdx.x;
    const int wid  = tid >> 5;
    const int lane = tid & 31;
    const int g = lane >> 2, t = lane & 3;
    const int m0 = (wid & 7) * 16;        // 8 warps over M=128
    const int n0 = (wid >> 3) * 56;       // 2 warps over N=112
    const uint32_t sb = smem_u32(sm);

    float2* ssc = (float2*)(sm + OFF_SS);
    const float* sscf = (const float*)ssc;

    // ---- prologue: BN fold + zero B buffers ----
    for (int c = tid; c < CIN; c += THREADS) {
        float inv = rsqrtf(rvar[c] + 1e-5f);
        float s = gamma[c] * inv;
        ssc[c] = make_float2(s, beta[c] - rmean[c] * s);
    }
    for (int i = tid; i < 2 * B_WORDS; i += THREADS) sm[OFF_B0 + i] = 0u;

    // ---- per-thread staging constants: 784 pair-slots = 8p x 98n, 2 iters ----
    int xoff[2], bsts[2], klr[2];
    #pragma unroll
    for (int j = 0; j < 2; j++) {
        int i = tid + j * THREADS;
        if (i > 783) i = 783;
        int p = i / 98;
        int n = i - 98 * p;
        int tp = p & 3, ks = p >> 2;
        int kl = ks * 16 + tp * 2;
        int b = (n >= HW) ? 1 : 0;
        int s = n - HW * b;
        xoff[j] = (b * CIN + kl) * HW + s;
        bsts[j] = n * LDB + 2 * ((p + ((n >> 2) & 7)) & 7);
        klr[j]  = kl;
    }
    const bool v1 = (tid < 272);          // iter1 valid for i<784

    // A cp.async: 512 quads = 128 m x 4 q, exactly 1 per thread
    const int am = tid >> 2, aq = tid & 3;
    const __half* a_src = W16_buf + am * CIN + aq * 8;
    const uint32_t a_db = (am * LDA + aq * 4) * 4;

    const float* xb = x + (size_t)blockIdx.x * NB * CIN * HW;
    __syncthreads();

    float acc[7][4];
    #pragma unroll
    for (int nt = 0; nt < 7; nt++)
        #pragma unroll
        for (int i = 0; i < 4; i++) acc[nt][i] = 0.0f;

    const int ar00 = (m0 + g) * LDA;
    const int ar01 = (m0 + g + 8) * LDA;
    const int bnb  = (n0 + g) * LDB;
    const int csl  = (n0 >> 2) + (g >> 2);

    float xv[2][4];

    #pragma unroll 1
    for (int kc = -1; kc < NKC; kc++) {
        const int kcn = kc + 1;

        // ---- cp.async A(kcn) into the free buffer ----
        if (kcn < NKC) {
            const uint32_t abase = sb + ((kcn & 1) ? OFF_A1 : OFF_A0) * 4;
            cp16(abase + a_db, a_src + kcn * KC);
        }
        asm volatile("cp.async.commit_group;" ::: "memory");

        // ---- x LDGs for chunk kcn ----
        if (kcn < NKC) {
            const int xadd = kcn * (KC * HW);
            #pragma unroll
            for (int j = 0; j < 2; j++) {
                if (j == 0 || v1) {
                    const float* px = xb + xoff[j] + xadd;
                    xv[j][0] = px[0];
                    xv[j][1] = px[HW];
                    xv[j][2] = px[8 * HW];
                    xv[j][3] = px[9 * HW];
                }
            }
        }

        // ---- MMA on chunk kc ----
        if (kc >= 0) {
            const uint32_t* As = sm + ((kc & 1) ? OFF_A1 : OFF_A0);
            const uint32_t* Bs = sm + ((kc & 1) ? OFF_B1 : OFF_B0);
            #pragma unroll
            for (int ks = 0; ks < 2; ks++) {
                const int ka = ks * 8 + t;
                uint32_t a0[4];
                a0[0] = As[ar00 + ka];     a0[1] = As[ar01 + ka];
                a0[2] = As[ar00 + ka + 4]; a0[3] = As[ar01 + ka + 4];
                const int pr = ks * 4 + t;
                #pragma unroll
                for (int nt = 0; nt < 7; nt++) {
                    const int slot = (pr + csl + 2 * nt) & 7;
                    uint2 b = *(const uint2*)&Bs[bnb + nt * 8 * LDB + 2 * slot];
                    hmma16816(acc[nt], a0[0], a0[1], a0[2], a0[3], b.x, b.y);
                }
            }
        }

        // A(kcn) landed before barrier
        asm volatile("cp.async.wait_group 0;" ::: "memory");

        // ---- BN + ReLU + cvt + STS chunk kcn ----
        if (kcn < NKC) {
            uint32_t* Bn = sm + ((kcn & 1) ? OFF_B1 : OFF_B0);
            const int kcb = kcn * KC;
            #pragma unroll
            for (int j = 0; j < 2; j++) {
                if (j == 0 || v1) {
                    const int c = kcb + klr[j];
                    float4 s0 = *(const float4*)(sscf + 2 * c);
                    float4 s1 = *(const float4*)(sscf + 2 * (c + 8));
                    float h0 = fmaxf(fmaf(xv[j][0], s0.x, s0.y), 0.0f);
                    float h1 = fmaxf(fmaf(xv[j][1], s0.z, s0.w), 0.0f);
                    float h2 = fmaxf(fmaf(xv[j][2], s1.x, s1.y), 0.0f);
                    float h3 = fmaxf(fmaf(xv[j][3], s1.z, s1.w), 0.0f);
                    uint2 hb;
                    hb.x = pack_h2(h0, h1);
                    hb.y = pack_h2(h2, h3);
                    *(uint2*)(Bn + bsts[j]) = hb;
                }
            }
        }
        __syncthreads();
    }

    // ---- epilogue: acc -> SMEM payload -> coalesced vector STG ----
    float* P = (float*)sm;
    {
        const int rb = m0 + g;
        #pragma unroll
        for (int nt = 0; nt < 7; nt++) {
            const int cb = n0 + nt * 8 + 2 * t;
            P[rb * PS + cb]           = acc[nt][0];
            P[rb * PS + cb + 1]       = acc[nt][1];
            P[(rb + 8) * PS + cb]     = acc[nt][2];
            P[(rb + 8) * PS + cb + 1] = acc[nt][3];
        }
    }
    __syncthreads();

    float* ob = out + (size_t)blockIdx.x * NB * COUT * HW;
    #pragma unroll
    for (int it = 0; it < 7; it++) {
        int f0 = (tid + it * THREADS) * 4;
        if (f0 < NB * COUT * HW) {
            float4 v;
            #pragma unroll
            for (int e = 0; e < 4; e++) {
                int f = f0 + e;
                int b = (f >= COUT * HW) ? 1 : 0;
                int r = f - b * (COUT * HW);
                int o = r / HW;
                int s = r - o * HW;
                ((float*)&v)[e] = P[o * PS + b * HW + s];
            }
            *(float4*)(ob + f0) = v;
        }
    }
}

extern "C" void kernel_launch(void* const* d_in, const int* in_sizes, int n_in,
                              void* d_out, int out_size)
{
    const float* x     = (const float*)d_in[0];
    const float* gamma = (const float*)d_in[1];
    const float* beta  = (const float*)d_in[2];
    const float* rmean = (const float*)d_in[3];
    const float* rvar  = (const float*)d_in[4];
    const float* W     = (const float*)d_in[5];
    float* out = (float*)d_out;

    w_cvt_kernel<<<84, 256>>>(W);
    cudaFuncSetAttribute(bn_conv_w32,
                         cudaFuncAttributeMaxDynamicSharedMemorySize, SMEM_BYTES);
    bn_conv_w32<<<GRID, THREADS, SMEM_BYTES>>>(x, gamma, beta, rmean, rvar, out);
}

// round 12
// speedup vs baseline: 1.0236x; 1.0236x over previous
#include <cuda_runtime.h>
#include <cuda_fp16.h>
#include <cstdint>

#define CIN   672
#define COUT  128
#define HW    49
#define NB    2
#define NREAL 98          // NB*HW
#define NPAD  112
#define KC    32
#define NKC   21
#define GRID  512
#define THREADS 128

#define LDA 20            // A row stride (half2 words): conflict-free frag reads
#define LDB 24            // B row stride (half2 words)
#define A_WORDS (COUT*LDA)   // 2560
#define B_WORDS (NPAD*LDB)   // 2688

#define OFF_SS 0                         // float2[672] = 1344 words
#define OFF_A0 1344
#define OFF_A1 (OFF_A0 + A_WORDS)
#define OFF_B0 (OFF_A1 + A_WORDS)
#define OFF_B1 (OFF_B0 + B_WORDS)
#define PIPE_WORDS (OFF_B1 + B_WORDS)    // 11840 words
#define PS 113
#define P_WORDS (COUT*PS)                // 14464 words
#define SMEM_WORDS (P_WORDS > PIPE_WORDS ? P_WORDS : PIPE_WORDS)
#define SMEM_BYTES (SMEM_WORDS*4)        // 57856 -> 2 CTAs/SM

// ---- fp16 copy of W, produced once by K0 ----
__device__ __align__(16) __half W16_buf[COUT * CIN];

__global__ void w_cvt_kernel(const float* __restrict__ W) {
    int i = blockIdx.x * 256 + threadIdx.x;      // 84*256 = 21504 = 86016/4
    float4 v = *(const float4*)(W + i * 4);
    __half2 h0 = __floats2half2_rn(v.x, v.y);
    __half2 h1 = __floats2half2_rn(v.z, v.w);
    uint2 q;
    q.x = *(uint32_t*)&h0;
    q.y = *(uint32_t*)&h1;
    *(uint2*)(W16_buf + i * 4) = q;
}

__device__ __forceinline__ void hmma16816(float c[4],
    uint32_t a0, uint32_t a1, uint32_t a2, uint32_t a3, uint32_t b0, uint32_t b1)
{
    asm volatile(
        "mma.sync.aligned.m16n8k16.row.col.f32.f16.f16.f32 "
        "{%0,%1,%2,%3}, {%4,%5,%6,%7}, {%8,%9}, {%0,%1,%2,%3};"
        : "+f"(c[0]), "+f"(c[1]), "+f"(c[2]), "+f"(c[3])
        : "r"(a0), "r"(a1), "r"(a2), "r"(a3), "r"(b0), "r"(b1));
}
__device__ __forceinline__ uint32_t pack_h2(float lo, float hi) {
    __half2 h = __floats2half2_rn(lo, hi);
    return *reinterpret_cast<uint32_t*>(&h);
}
__device__ __forceinline__ uint32_t smem_u32(const void* p) {
    uint32_t a;
    asm("{ .reg .u64 t; cvta.to.shared.u64 t, %1; cvt.u32.u64 %0, t; }" : "=r"(a) : "l"(p));
    return a;
}
__device__ __forceinline__ void cp16(uint32_t dst, const void* src) {
    asm volatile("cp.async.cg.shared.global [%0], [%1], 16;" :: "r"(dst), "l"(src) : "memory");
}

extern __shared__ uint32_t sm[];

__global__ void __launch_bounds__(THREADS, 2)
bn_conv_ilp(const float* __restrict__ x,
            const float* __restrict__ gamma,
            const float* __restrict__ beta,
            const float* __restrict__ rmean,
            const float* __restrict__ rvar,
            float* __restrict__ out)
{
    const int tid  = threadIdx.x;
    const int wid  = tid >> 5;
    const int lane = tid & 31;
    const int g = lane >> 2, t = lane & 3;
    const int m0 = (wid & 1) * 64;        // 2 warps over M=128 (4 m16 tiles each)
    const int n0 = (wid >> 1) * 56;       // 2 warps over N=112
    const uint32_t sb = smem_u32(sm);

    float2* ssc = (float2*)(sm + OFF_SS);
    const float* sscf = (const float*)ssc;

    // ---- prologue: BN fold + zero B buffers ----
    for (int c = tid; c < CIN; c += THREADS) {
        float inv = rsqrtf(rvar[c] + 1e-5f);
        float s = gamma[c] * inv;
        ssc[c] = make_float2(s, beta[c] - rmean[c] * s);
    }
    for (int i = tid; i < 2 * B_WORDS; i += THREADS) sm[OFF_B0 + i] = 0u;

    // ---- per-thread staging constants: 784 pair-slots = 8p x 98n, 7 iters ----
    int xoff[7], bsk[7];                   // bsk = bsts | (kl<<20)
    #pragma unroll
    for (int j = 0; j < 7; j++) {
        int i = tid + j * THREADS;
        if (i > 783) i = 783;
        int p = i / 98;
        int n = i - 98 * p;
        int tp = p & 3, ks = p >> 2;
        int kl = ks * 16 + tp * 2;
        int b = (n >= HW) ? 1 : 0;
        int s = n - HW * b;
        xoff[j] = (b * CIN + kl) * HW + s;
        bsk[j]  = (n * LDB + 2 * ((p + ((n >> 2) & 7)) & 7)) | (kl << 20);
    }
    const bool v6 = (tid < 16);           // iter 6 valid for i<784

    // A cp.async: 512 quads = 128 m x 4 q, 4 per thread
    const __half* a_src[4];
    uint32_t a_db[4];
    #pragma unroll
    for (int i = 0; i < 4; i++) {
        int ia = tid + i * THREADS;
        int m = ia >> 2, q = ia & 3;
        a_src[i] = W16_buf + m * CIN + q * 8;
        a_db[i]  = (m * LDA + q * 4) * 4;
    }

    const float* xb = x + (size_t)blockIdx.x * NB * CIN * HW;
    __syncthreads();

    float acc[4][7][4];
    #pragma unroll
    for (int mt = 0; mt < 4; mt++)
        #pragma unroll
        for (int nt = 0; nt < 7; nt++)
            #pragma unroll
            for (int i = 0; i < 4; i++) acc[mt][nt][i] = 0.0f;

    const int arg = (m0 + g) * LDA;       // mt rows: + mt*16*LDA (+8*LDA for hi)
    const int bnb = (n0 + g) * LDB;
    const int csl = (n0 >> 2) + (g >> 2);

    float xv[7][4];

    #pragma unroll 1
    for (int kc = -1; kc < NKC; kc++) {
        const int kcn = kc + 1;

        // ---- cp.async A(kcn) into the free buffer ----
        if (kcn < NKC) {
            const uint32_t abase = sb + ((kcn & 1) ? OFF_A1 : OFF_A0) * 4;
            #pragma unroll
            for (int i = 0; i < 4; i++)
                cp16(abase + a_db[i], a_src[i] + kcn * KC);
        }
        asm volatile("cp.async.commit_group;" ::: "memory");

        // ---- x LDGs for chunk kcn ----
        if (kcn < NKC) {
            const int xadd = kcn * (KC * HW);
            #pragma unroll
            for (int j = 0; j < 7; j++) {
                if (j < 6 || v6) {
                    const float* px = xb + xoff[j] + xadd;
                    xv[j][0] = px[0];
                    xv[j][1] = px[HW];
                    xv[j][2] = px[8 * HW];
                    xv[j][3] = px[9 * HW];
                }
            }
        }

        // ---- MMA on chunk kc: 4 mt x 7 nt x 2 ks = 56 HMMA ----
        if (kc >= 0) {
            const uint32_t* As = sm + ((kc & 1) ? OFF_A1 : OFF_A0);
            const uint32_t* Bs = sm + ((kc & 1) ? OFF_B1 : OFF_B0);
            #pragma unroll
            for (int ks = 0; ks < 2; ks++) {
                const int ka = ks * 8 + t;
                uint32_t a[4][4];
                #pragma unroll
                for (int mt = 0; mt < 4; mt++) {
                    const int r0 = arg + mt * 16 * LDA;
                    a[mt][0] = As[r0 + ka];
                    a[mt][1] = As[r0 + 8 * LDA + ka];
                    a[mt][2] = As[r0 + ka + 4];
                    a[mt][3] = As[r0 + 8 * LDA + ka + 4];
                }
                const int pr = ks * 4 + t;
                #pragma unroll
                for (int nt = 0; nt < 7; nt++) {
                    const int slot = (pr + csl + 2 * nt) & 7;
                    uint2 b = *(const uint2*)&Bs[bnb + nt * 8 * LDB + 2 * slot];
                    #pragma unroll
                    for (int mt = 0; mt < 4; mt++)
                        hmma16816(acc[mt][nt], a[mt][0], a[mt][1], a[mt][2], a[mt][3], b.x, b.y);
                }
            }
        }

        // A(kcn) landed before barrier
        asm volatile("cp.async.wait_group 0;" ::: "memory");

        // ---- BN + ReLU + cvt + STS chunk kcn ----
        if (kcn < NKC) {
            uint32_t* Bn = sm + ((kcn & 1) ? OFF_B1 : OFF_B0);
            const int kcb = kcn * KC;
            #pragma unroll
            for (int j = 0; j < 7; j++) {
                if (j < 6 || v6) {
                    const int c = kcb + (bsk[j] >> 20);
                    float4 s0 = *(const float4*)(sscf + 2 * c);
                    float4 s1 = *(const float4*)(sscf + 2 * (c + 8));
                    float h0 = fmaxf(fmaf(xv[j][0], s0.x, s0.y), 0.0f);
                    float h1 = fmaxf(fmaf(xv[j][1], s0.z, s0.w), 0.0f);
                    float h2 = fmaxf(fmaf(xv[j][2], s1.x, s1.y), 0.0f);
                    float h3 = fmaxf(fmaf(xv[j][3], s1.z, s1.w), 0.0f);
                    uint2 hb;
                    hb.x = pack_h2(h0, h1);
                    hb.y = pack_h2(h2, h3);
                    *(uint2*)(Bn + (bsk[j] & 0xFFFFF)) = hb;
                }
            }
        }
        __syncthreads();
    }

    // ---- epilogue: acc -> SMEM payload -> coalesced vector STG ----
    float* P = (float*)sm;
    #pragma unroll
    for (int mt = 0; mt < 4; mt++) {
        const int rb = m0 + mt * 16 + g;
        #pragma unroll
        for (int nt = 0; nt < 7; nt++) {
            const int cb = n0 + nt * 8 + 2 * t;
            P[rb * PS + cb]           = acc[mt][nt][0];
            P[rb * PS + cb + 1]       = acc[mt][nt][1];
            P[(rb + 8) * PS + cb]     = acc[mt][nt][2];
            P[(rb + 8) * PS + cb + 1] = acc[mt][nt][3];
        }
    }
    __syncthreads();

    float* ob = out + (size_t)blockIdx.x * NB * COUT * HW;
    #pragma unroll
    for (int it = 0; it < 25; it++) {
        int f0 = (tid + it * THREADS) * 4;
        if (f0 < NB * COUT * HW) {
            float4 v;
            #pragma unroll
            for (int e = 0; e < 4; e++) {
                int f = f0 + e;
                int b = (f >= COUT * HW) ? 1 : 0;
                int r = f - b * (COUT * HW);
                int o = r / HW;
                int s = r - o * HW;
                ((float*)&v)[e] = P[o * PS + b * HW + s];
            }
            *(float4*)(ob + f0) = v;
        }
    }
}

extern "C" void kernel_launch(void* const* d_in, const int* in_sizes, int n_in,
                              void* d_out, int out_size)
{
    const float* x     = (const float*)d_in[0];
    const float* gamma = (const float*)d_in[1];
    const float* beta  = (const float*)d_in[2];
    const float* rmean = (const float*)d_in[3];
    const float* rvar  = (const float*)d_in[4];
    const float* W     = (const float*)d_in[5];
    float* out = (float*)d_out;

    w_cvt_kernel<<<84, 256>>>(W);
    cudaFuncSetAttribute(bn_conv_ilp,
                         cudaFuncAttributeMaxDynamicSharedMemorySize, SMEM_BYTES);
    bn_conv_ilp<<<GRID, THREADS, SMEM_BYTES>>>(x, gamma, beta, rmean, rvar, out);
}